// round 13
// baseline (speedup 1.0000x reference)
#include <cuda_runtime.h>
#include <math.h>

#define NANCH 49104
#define NCLS  90
#define NBATCH 8
#define NTASK (NBATCH * NCLS)   // 720
#define KPRE  5000
#define KPOST 100
#define KBATCH 256              // fallback per-batch select size
#define CKCAP 1024              // bucket capacity / sort size
#define TSK_T 128
#define FLB_T 512
#define FIN_T 512
#define FAST_LOGIT 2.2f         // fast-path threshold (count ~680 << 1024)

typedef unsigned long long u64;

// ---------------- scratch (zero-initialized at module load) ----------------
__device__ int      g_cnt[NTASK];
__device__ int      g_ok[NTASK];
__device__ u64      g_bucket[(size_t)NTASK * CKCAP];    // (f2key(sigmoid)<<17 | 131071-n)
__device__ float4   g_nms_boxes[NTASK * KPOST];
__device__ float    g_nms_scores[NTASK * KPOST];

__constant__ int c_lvl_off[6]    = {0, 36864, 46080, 48384, 48960, 49104};
__constant__ int c_lvl_feat[5]   = {64, 32, 16, 8, 4};
__constant__ int c_lvl_stride[5] = {8, 16, 32, 64, 128};

__device__ __forceinline__ unsigned f2key(float f) {
    unsigned u = __float_as_uint(f);
    return (u & 0x80000000u) ? ~u : (u | 0x80000000u);
}
__device__ __forceinline__ float key2f(unsigned k) {
    unsigned u = (k & 0x80000000u) ? (k ^ 0x80000000u) : ~k;
    return __uint_as_float(u);
}

__device__ __forceinline__ bool iou_gt(const float4 a, const float4 b) {
    float yy1 = fmaxf(a.x, b.x), xx1 = fmaxf(a.y, b.y);
    float yy2 = fminf(a.z, b.z), xx2 = fminf(a.w, b.w);
    float ih = fmaxf(__fsub_rn(yy2, yy1), 0.0f);
    float iw = fmaxf(__fsub_rn(xx2, xx1), 0.0f);
    float inter = __fmul_rn(ih, iw);
    float a1 = __fmul_rn(__fsub_rn(a.z, a.x), __fsub_rn(a.w, a.y));
    float a2 = __fmul_rn(__fsub_rn(b.z, b.x), __fsub_rn(b.w, b.y));
    float den = __fadd_rn(__fsub_rn(__fadd_rn(a1, a2), inter), 1e-8f);
    return __fdiv_rn(inter, den) > 0.5f;
}

// inclusive SUFFIX scan over 512 per-thread values (blockDim must be 512)
__device__ __forceinline__ unsigned sufscan512(unsigned ssum, unsigned* wA, unsigned* wB) {
    int lane = threadIdx.x & 31, wrp = threadIdx.x >> 5;
    unsigned s = ssum;
    #pragma unroll
    for (int o = 1; o < 32; o <<= 1) {
        unsigned t = __shfl_down_sync(0xffffffffu, s, o);
        if (lane + o < 32) s += t;
    }
    if (lane == 0) wA[wrp] = s;
    __syncthreads();
    if (threadIdx.x < 32) {
        unsigned v = (threadIdx.x < 16) ? wA[threadIdx.x] : 0u;
        unsigned sv = v;
        #pragma unroll
        for (int o = 1; o < 32; o <<= 1) {
            unsigned t = __shfl_down_sync(0xffffffffu, sv, o);
            if (threadIdx.x + o < 32) sv += t;
        }
        if (threadIdx.x < 16) wB[threadIdx.x] = sv - v;
    }
    __syncthreads();
    return s + wB[wrp];
}

__device__ __forceinline__ float4 decode_box(int n, const float4* __restrict__ deltas,
                                             int b, const float* s_hh, const float* s_hw) {
    int l = 0;
    #pragma unroll
    for (int q = 1; q < 5; ++q) if (n >= c_lvl_off[q]) l = q;
    int j    = n - c_lvl_off[l];
    int cell = j / 9, a = j - cell * 9;
    int feat = c_lvl_feat[l];
    int row  = cell / feat, col = cell - row * feat;
    int stride = c_lvl_stride[l];

    float hh = s_hh[l * 9 + a];
    float hw = s_hw[l * 9 + a];

    float cy = ((float)row + 0.5f) * (float)stride;
    float cx = ((float)col + 0.5f) * (float)stride;
    float ay1 = __fsub_rn(cy, hh), ay2 = __fadd_rn(cy, hh);
    float ax1 = __fsub_rn(cx, hw), ax2 = __fadd_rn(cx, hw);
    float ah  = __fsub_rn(ay2, ay1), aw = __fsub_rn(ax2, ax1);
    float acy = __fmul_rn(__fadd_rn(ay1, ay2), 0.5f);
    float acx = __fmul_rn(__fadd_rn(ax1, ax2), 0.5f);

    float4 d = __ldg(deltas + (size_t)b * NANCH + n);
    float ncy = __fadd_rn(__fmul_rn(d.x, ah), acy);
    float ncx = __fadd_rn(__fmul_rn(d.y, aw), acx);
    float h   = __fmul_rn(expf(d.z), ah);
    float w   = __fmul_rn(expf(d.w), aw);

    const float inv = 1.0f / 512.0f;
    float y1 = __fsub_rn(ncy, __fmul_rn(h, 0.5f)) * inv;
    float x1 = __fsub_rn(ncx, __fmul_rn(w, 0.5f)) * inv;
    float y2 = __fadd_rn(ncy, __fmul_rn(h, 0.5f)) * inv;
    float x2 = __fadd_rn(ncx, __fmul_rn(w, 0.5f)) * inv;
    y1 = fminf(fmaxf(y1, 0.0f), 1.0f);
    x1 = fminf(fmaxf(x1, 0.0f), 1.0f);
    y2 = fminf(fmaxf(y2, 0.0f), 1.0f);
    x2 = fminf(fmaxf(x2, 0.0f), 1.0f);
    return make_float4(y1, x1, y2, x2);
}

// raw logit key in transposed order (fallback only; never hot)
__device__ __forceinline__ unsigned ldkey(const float* __restrict__ logits,
                                          int b, int c, int i) {
    return f2key(__ldg(logits + ((size_t)b * NANCH + i) * NCLS + c));
}

// ---------------- kernel 1: filter — flat float4 stream, scatter final sort keys ----------------
__global__ void __launch_bounds__(256) k_filter(const float4* __restrict__ logits4) {
    const int total4 = NBATCH * NANCH * NCLS / 4;   // 8,838,720
    int stride = gridDim.x * blockDim.x;
    for (int i = blockIdx.x * blockDim.x + threadIdx.x; i < total4; i += stride) {
        float4 v = __ldg(logits4 + i);
        int fbase = i * 4;
        #pragma unroll
        for (int q = 0; q < 4; ++q) {
            float lg = (q == 0) ? v.x : (q == 1) ? v.y : (q == 2) ? v.z : v.w;
            if (lg > FAST_LOGIT) {
                int fidx = fbase + q;
                int a = fidx / NCLS;
                int c = fidx - a * NCLS;
                int b = a / NANCH;
                int n = a - b * NANCH;
                int task = b * NCLS + c;
                int slot = atomicAdd(&g_cnt[task], 1);
                if (slot < CKCAP) {
                    float sc = __fdiv_rn(1.0f, __fadd_rn(1.0f, expf(-lg)));
                    g_bucket[(size_t)task * CKCAP + slot] =
                        ((u64)f2key(sc) << 17) | (u64)(131071 - n);
                }
            }
        }
    }
}

// ---------------- kernel 2: fast path — 128 thr, full sort + register-list scan ----------------
__global__ void __launch_bounds__(TSK_T) k_task(const float4* __restrict__ deltas) {
    __shared__ u64    ck[CKCAP];       //  8 KB
    __shared__ float4 cboxes[CKCAP];   // 16 KB
    __shared__ float  s_hh[45], s_hw[45];
    __shared__ int s_cnt, s_na, s_ok;

    int tid  = threadIdx.x;
    int lane = tid & 31;
    int task = blockIdx.x;
    int b    = task / NCLS;

    if (tid < 45) {
        int l = tid / 9, a = tid - l * 9;
        int stride = c_lvl_stride[l];
        int iscale = a / 3, ri = a - iscale * 3;
        double rr   = (ri == 0) ? 1.0 : (ri == 1 ? 0.5 : 2.0);
        double base = exp2((double)iscale / 3.0) * (double)stride * 4.0;
        double sq   = sqrt(rr);
        s_hh[tid] = (float)(base / sq / 2.0);
        s_hw[tid] = (float)(base * sq / 2.0);
    }
    if (tid == 0) { s_cnt = g_cnt[task]; g_cnt[task] = 0; }   // read + reset for next replay
    __syncthreads();
    int cnt = s_cnt;

    if (cnt > CKCAP) {                     // overflow -> exact fallback kernel
        if (tid == 0) g_ok[task] = 0;
        return;
    }

    // load bucket keys (already final sort keys)
    const u64* bk = g_bucket + (size_t)task * CKCAP;
    #pragma unroll
    for (int s = 0; s < CKCAP / TSK_T; ++s) {
        int i = tid + s * TSK_T;
        ck[i] = (i < cnt) ? __ldg(bk + i) : 0ull;
    }
    __syncthreads();

    // block-wide bitonic sort of 1024, descending (4 pairs/thread/round)
    for (int k2 = 2; k2 <= CKCAP; k2 <<= 1) {
        for (int j = k2 >> 1; j > 0; j >>= 1) {
            #pragma unroll
            for (int s = 0; s < CKCAP / (2 * TSK_T); ++s) {
                int p  = tid + s * TSK_T;
                int i  = ((p & ~(j - 1)) << 1) | (p & (j - 1));
                int ix = i | j;
                u64 a = ck[i], b2 = ck[ix];
                bool asc = ((i & k2) == 0);
                if ((a < b2) == asc) { ck[i] = b2; ck[ix] = a; }
            }
            __syncthreads();
        }
    }

    // decode boxes (sorted order)
    #pragma unroll
    for (int s = 0; s < CKCAP / TSK_T; ++s) {
        int i = tid + s * TSK_T;
        u64 k = ck[i];
        if (k) {
            int n = 131071 - (int)(k & 131071ull);
            cboxes[i] = decode_box(n, deltas, b, s_hh, s_hw);
        }
    }
    __syncthreads();

    // warp 0: linear sorted scan; accepted boxes held in registers
    // lane L holds accepted positions L, L+32, L+64, L+96
    if (tid < 32) {
        float4 ab0 = make_float4(0.f,0.f,0.f,0.f), ab1 = ab0, ab2 = ab0, ab3 = ab0;
        int cna = 0, dn = 0;
        size_t obase = (size_t)task * KPOST;
        for (int f = 0; f < cnt; ++f) {
            u64 kk = ck[f];
            float sc = key2f((unsigned)(kk >> 17));
            if (!(sc > 0.2f)) { dn = 1; break; }
            float4 box = cboxes[f];
            bool sup = false;
            if (lane < cna) {
                sup = iou_gt(ab0, box);
                if (!sup && lane + 32 < cna) sup = iou_gt(ab1, box);
                if (!sup && lane + 64 < cna) sup = iou_gt(ab2, box);
                if (!sup && lane + 96 < cna) sup = iou_gt(ab3, box);
            }
            if (!__any_sync(0xffffffffu, sup)) {
                if (lane == (cna & 31)) {
                    int slot = cna >> 5;
                    if (slot == 0) ab0 = box;
                    else if (slot == 1) ab1 = box;
                    else if (slot == 2) ab2 = box;
                    else ab3 = box;
                }
                if (lane == 0) {
                    g_nms_scores[obase + cna] = sc;
                    g_nms_boxes [obase + cna] = box;
                }
                cna++;
                if (cna == KPOST) { dn = 1; break; }
            }
        }
        if (lane == 0) { s_na = cna; s_ok = dn; }
    }
    __syncthreads();
    if (tid == 0) g_ok[task] = s_ok;
    if (s_ok) {
        for (int q = s_na + tid; q < KPOST; q += TSK_T) {
            g_nms_scores[(size_t)task * KPOST + q] = 0.0f;
            g_nms_boxes [(size_t)task * KPOST + q] = make_float4(0.f, 0.f, 0.f, 0.f);
        }
    }
}

// ---------------- kernel 2b: exact fallback (early-exit when fast path succeeded) ----------------
__global__ void __launch_bounds__(FLB_T) k_fallback(const float4* __restrict__ deltas,
                                                    const float* __restrict__ logits) {
    int task = blockIdx.x;
    if (g_ok[task]) return;                 // uniform per block

    __shared__ unsigned hist[2048];
    __shared__ u64      ck[CKCAP];
    __shared__ float4   cboxes[CKCAP];
    __shared__ float4   s_abox[KPOST];
    __shared__ unsigned wA[16], wB[16];
    __shared__ float    s_hh[45], s_hw[45];
    __shared__ int s_bcv, s_bck, s_cnt, s_na, s_done;
    __shared__ unsigned s_total;

    int tid  = threadIdx.x;
    int lane = tid & 31;
    int b    = task / NCLS;
    int c    = task - b * NCLS;

    if (tid < 45) {
        int l = tid / 9, a = tid - l * 9;
        int stride = c_lvl_stride[l];
        int iscale = a / 3, ri = a - iscale * 3;
        double rr   = (ri == 0) ? 1.0 : (ri == 1 ? 0.5 : 2.0);
        double base = exp2((double)iscale / 3.0) * (double)stride * 4.0;
        double sq   = sqrt(rr);
        s_hh[tid] = (float)(base / sq / 2.0);
        s_hw[tid] = (float)(base * sq / 2.0);
    }
    if (tid == 0) { s_na = 0; s_done = 0; }
    __syncthreads();

    unsigned Tprev = 0;
    bool first = true;
    int cand_base = 0;

    for (;;) {
        unsigned prefix = 0;
        int Krem = KBATCH;
        bool allin = false;
        const int SH[3] = {21, 10, 0};
        const int BT[3] = {11, 11, 10};
        for (int pass = 0; pass < 3; ++pass) {
            int shift = SH[pass], bits = BT[pass], nb = 1 << bits, top = shift + bits;
            for (int i = tid; i < nb; i += FLB_T) hist[i] = 0;
            __syncthreads();
            for (int base = 0; base < NANCH; base += FLB_T) {
                int i = base + tid;
                bool inb = i < NANCH;
                unsigned k = inb ? ldkey(logits, b, c, i) : 0u;
                bool valid = inb && (first || k < Tprev) &&
                             (pass == 0 || (k >> top) == prefix);
                unsigned bin = (k >> shift) & (unsigned)(nb - 1);
                unsigned tag = valid ? bin : 0xffffffffu;
                unsigned m = __match_any_sync(0xffffffffu, tag);
                if (valid && (__ffs(m) - 1) == lane)
                    atomicAdd(&hist[bin], (unsigned)__popc(m));
            }
            __syncthreads();
            int cs = nb >> 9;
            int base0 = tid * cs;
            unsigned ssum = 0;
            for (int j = 0; j < cs; ++j) ssum += hist[base0 + j];
            unsigned St = sufscan512(ssum, wA, wB);
            if (pass == 0 && tid == 0) s_total = St;
            if (St >= (unsigned)Krem && (St - ssum) < (unsigned)Krem) {
                unsigned acc = St - ssum;
                for (int j = cs - 1; j >= 0; --j) {
                    unsigned hv = hist[base0 + j];
                    acc += hv;
                    if (acc >= (unsigned)Krem) {
                        s_bcv = base0 + j;
                        s_bck = Krem - (int)(acc - hv);
                        break;
                    }
                }
            }
            __syncthreads();
            if (pass == 0 && s_total <= (unsigned)KBATCH) { allin = true; break; }
            prefix = (prefix << bits) | (unsigned)s_bcv;
            Krem   = s_bck;
            __syncthreads();
        }
        unsigned T = allin ? 0u : prefix;

        if (tid == 0) s_cnt = 0;
        __syncthreads();
        for (int base = 0; base < NANCH; base += FLB_T) {
            int i = base + tid;
            bool inb = i < NANCH;
            unsigned k = inb ? ldkey(logits, b, c, i) : 0u;
            bool pred = inb && (first || k < Tprev) && (k >= T);
            unsigned mask = __ballot_sync(0xffffffffu, pred);
            if (pred) {
                int leader = __ffs(mask) - 1;
                int bslot = 0;
                if (lane == leader) bslot = atomicAdd(&s_cnt, __popc(mask));
                bslot = __shfl_sync(mask, bslot, leader);
                int slot = bslot + __popc(mask & ((1u << lane) - 1u));
                if (slot < CKCAP) {
                    float logit = key2f(k);
                    float sc = __fdiv_rn(1.0f, __fadd_rn(1.0f, expf(-logit)));
                    ck[slot] = ((u64)f2key(sc) << 17) | (u64)(131071 - i);
                }
            }
        }
        __syncthreads();
        int M = min(s_cnt, CKCAP);
        for (int i = M + tid; i < CKCAP; i += FLB_T) ck[i] = 0ull;
        __syncthreads();

        for (int k2 = 2; k2 <= CKCAP; k2 <<= 1) {
            for (int j = k2 >> 1; j > 0; j >>= 1) {
                int i  = ((tid & ~(j - 1)) << 1) | (tid & (j - 1));
                int ix = i | j;
                bool asc = ((i & k2) == 0);
                u64 a = ck[i], b2 = ck[ix];
                if ((a < b2) == asc) { ck[i] = b2; ck[ix] = a; }
                __syncthreads();
            }
        }

        for (int i = tid; i < M; i += FLB_T) {
            int n = 131071 - (int)(ck[i] & 131071ull);
            cboxes[i] = decode_box(n, deltas, b, s_hh, s_hw);
        }
        __syncthreads();

        if (tid < 32) {
            int cna = s_na;
            int dn  = 0;
            for (int f = 0; f < M; ++f) {
                if (cand_base + f >= KPRE) { dn = 1; break; }
                u64 kk = ck[f];
                float sc = key2f((unsigned)(kk >> 17));
                if (!(sc > 0.2f)) { dn = 1; break; }
                float4 box = cboxes[f];
                bool sup = false;
                for (int a = lane; a < cna; a += 32)
                    if (iou_gt(s_abox[a], box)) { sup = true; break; }
                if (!__any_sync(0xffffffffu, sup)) {
                    if (lane == 0) {
                        g_nms_scores[(size_t)task * KPOST + cna] = sc;
                        g_nms_boxes [(size_t)task * KPOST + cna] = box;
                        s_abox[cna] = box;
                    }
                    __syncwarp();
                    cna++;
                    if (cna == KPOST) { dn = 1; break; }
                }
            }
            if (lane == 0) { s_na = cna; s_done = dn; }
        }
        __syncthreads();
        cand_base += M;
        if (s_done || allin || M == 0 || cand_base >= KPRE) break;
        Tprev = T;
        first = false;
        __syncthreads();
    }

    for (int q = s_na + tid; q < KPOST; q += FLB_T) {
        g_nms_scores[(size_t)task * KPOST + q] = 0.0f;
        g_nms_boxes [(size_t)task * KPOST + q] = make_float4(0.f, 0.f, 0.f, 0.f);
    }
}

// ---------------- kernel 3: per-batch top-100 of 9000 (radix select + rank) ----------------
extern __shared__ u64 smF[];
__global__ void __launch_bounds__(FIN_T) k_final(float* __restrict__ out) {
    u64*      ck   = smF;                             // [9000]
    unsigned* hist = (unsigned*)(smF + NCLS * KPOST); // [4096]
    __shared__ unsigned wA[16], wB[16];
    __shared__ int s_bcv, s_bck, s_cnt, s_valid;
    __shared__ u64 surv[KPOST];

    int b = blockIdx.x, tid = threadIdx.x;
    const float* src = g_nms_scores + (size_t)b * NCLS * KPOST;
    for (int i = tid; i < NCLS * KPOST; i += FIN_T)
        ck[i] = ((u64)f2key(src[i]) << 14) | (u64)(16383 - i);
    if (tid == 0) { s_cnt = 0; s_valid = 0; }
    __syncthreads();

    u64 pref = 0; int Krem = KPOST;
    const int SHs[4] = {34, 22, 10, 0};
    const int BTs[4] = {12, 12, 12, 10};
    for (int p = 0; p < 4; ++p) {
        int shift = SHs[p], bits = BTs[p], nb = 1 << bits, top = shift + bits;
        for (int i = tid; i < nb; i += FIN_T) hist[i] = 0;
        __syncthreads();
        for (int i = tid; i < NCLS * KPOST; i += FIN_T) {
            u64 k = ck[i];
            if ((k >> top) == pref)
                atomicAdd(&hist[(unsigned)((k >> shift) & (u64)(nb - 1))], 1u);
        }
        __syncthreads();
        int csz = nb >> 9; if (csz == 0) csz = 1;
        int base0 = tid * csz;
        unsigned ssum = 0;
        for (int j = 0; j < csz; ++j) ssum += hist[base0 + j];
        unsigned St = sufscan512(ssum, wA, wB);
        if (St >= (unsigned)Krem && (St - ssum) < (unsigned)Krem) {
            unsigned acc = St - ssum;
            for (int j = csz - 1; j >= 0; --j) {
                unsigned hv = hist[base0 + j];
                acc += hv;
                if (acc >= (unsigned)Krem) {
                    s_bcv = base0 + j;
                    s_bck = Krem - (int)(acc - hv);
                    break;
                }
            }
        }
        __syncthreads();
        pref = (pref << bits) | (u64)(unsigned)s_bcv;
        Krem = s_bck;
        __syncthreads();
    }
    u64 T = pref;

    for (int i = tid; i < NCLS * KPOST; i += FIN_T) {
        u64 k = ck[i];
        if (k >= T) {
            int slot = atomicAdd(&s_cnt, 1);
            if (slot < KPOST) surv[slot] = k;
        }
    }
    __syncthreads();

    if (tid < KPOST) {
        u64 k = surv[tid];
        int rank = 0;
        #pragma unroll 4
        for (int j = 0; j < KPOST; ++j) rank += (surv[j] > k);
        int flat = 16383 - (int)(k & 16383ull);
        float sc = key2f((unsigned)(k >> 14));
        float4 bb = g_nms_boxes[(size_t)b * NCLS * KPOST + flat];
        float* ob = out + ((size_t)b * KPOST + rank) * 4;
        ob[0] = bb.x; ob[1] = bb.y; ob[2] = bb.z; ob[3] = bb.w;
        out[NBATCH * KPOST * 4 + b * KPOST + rank] = sc;
        out[NBATCH * KPOST * 5 + b * KPOST + rank] = (float)(flat / KPOST);
        if (sc > 0.0f) atomicAdd(&s_valid, 1);
    }
    __syncthreads();
    if (tid == 0) out[NBATCH * KPOST * 6 + b] = (float)s_valid;
}

// ---------------- launch ----------------
extern "C" void kernel_launch(void* const* d_in, const int* in_sizes, int n_in,
                              void* d_out, int out_size) {
    const float* a0 = (const float*)d_in[0];
    const float* a1 = (const float*)d_in[1];
    const float4* deltas;
    const float*  logits;
    if (in_sizes[0] == NBATCH * NANCH * 4) { deltas = (const float4*)a0; logits = a1; }
    else                                   { deltas = (const float4*)a1; logits = a0; }
    float* out = (float*)d_out;

    const int finSm = NCLS * KPOST * 8 + 4096 * 4;   // 88,384
    cudaFuncSetAttribute(k_final, cudaFuncAttributeMaxDynamicSharedMemorySize, finSm);

    k_filter<<<4096, 256>>>((const float4*)logits);
    k_task<<<NTASK, TSK_T>>>(deltas);
    k_fallback<<<NTASK, FLB_T>>>(deltas, logits);
    k_final<<<NBATCH, FIN_T, finSm>>>(out);
}

// round 14
// speedup vs baseline: 1.1966x; 1.1966x over previous
#include <cuda_runtime.h>
#include <math.h>

#define NANCH 49104
#define NCLS  90
#define NBATCH 8
#define NTASK (NBATCH * NCLS)   // 720
#define KPRE  5000
#define KPOST 100
#define KBATCH 256              // fallback per-batch select size
#define CKCAP 1024              // bucket capacity / sort size
#define TSK_T 128
#define FLB_T 512
#define FIN_T 512
#define FAST_LOGIT 2.2f         // fast-path threshold (count ~680 << 1024)

typedef unsigned long long u64;

// ---------------- scratch (zero-initialized at module load) ----------------
__device__ int      g_cnt[NTASK];
__device__ int      g_ok[NTASK];
__device__ u64      g_bucket[(size_t)NTASK * CKCAP];    // (f2key(sigmoid)<<17 | 131071-n)
__device__ float4   g_nms_boxes[NTASK * KPOST];
__device__ float    g_nms_scores[NTASK * KPOST];

__constant__ int c_lvl_off[6]    = {0, 36864, 46080, 48384, 48960, 49104};
__constant__ int c_lvl_feat[5]   = {64, 32, 16, 8, 4};
__constant__ int c_lvl_stride[5] = {8, 16, 32, 64, 128};

__device__ __forceinline__ unsigned f2key(float f) {
    unsigned u = __float_as_uint(f);
    return (u & 0x80000000u) ? ~u : (u | 0x80000000u);
}
__device__ __forceinline__ float key2f(unsigned k) {
    unsigned u = (k & 0x80000000u) ? (k ^ 0x80000000u) : ~k;
    return __uint_as_float(u);
}

__device__ __forceinline__ bool iou_gt(const float4 a, const float4 b) {
    float yy1 = fmaxf(a.x, b.x), xx1 = fmaxf(a.y, b.y);
    float yy2 = fminf(a.z, b.z), xx2 = fminf(a.w, b.w);
    float ih = fmaxf(__fsub_rn(yy2, yy1), 0.0f);
    float iw = fmaxf(__fsub_rn(xx2, xx1), 0.0f);
    float inter = __fmul_rn(ih, iw);
    float a1 = __fmul_rn(__fsub_rn(a.z, a.x), __fsub_rn(a.w, a.y));
    float a2 = __fmul_rn(__fsub_rn(b.z, b.x), __fsub_rn(b.w, b.y));
    float den = __fadd_rn(__fsub_rn(__fadd_rn(a1, a2), inter), 1e-8f);
    return __fdiv_rn(inter, den) > 0.5f;
}

// inclusive SUFFIX scan over 512 per-thread values (blockDim must be 512)
__device__ __forceinline__ unsigned sufscan512(unsigned ssum, unsigned* wA, unsigned* wB) {
    int lane = threadIdx.x & 31, wrp = threadIdx.x >> 5;
    unsigned s = ssum;
    #pragma unroll
    for (int o = 1; o < 32; o <<= 1) {
        unsigned t = __shfl_down_sync(0xffffffffu, s, o);
        if (lane + o < 32) s += t;
    }
    if (lane == 0) wA[wrp] = s;
    __syncthreads();
    if (threadIdx.x < 32) {
        unsigned v = (threadIdx.x < 16) ? wA[threadIdx.x] : 0u;
        unsigned sv = v;
        #pragma unroll
        for (int o = 1; o < 32; o <<= 1) {
            unsigned t = __shfl_down_sync(0xffffffffu, sv, o);
            if (threadIdx.x + o < 32) sv += t;
        }
        if (threadIdx.x < 16) wB[threadIdx.x] = sv - v;
    }
    __syncthreads();
    return s + wB[wrp];
}

__device__ __forceinline__ float4 decode_box(int n, const float4* __restrict__ deltas,
                                             int b, const float* s_hh, const float* s_hw) {
    int l = 0;
    #pragma unroll
    for (int q = 1; q < 5; ++q) if (n >= c_lvl_off[q]) l = q;
    int j    = n - c_lvl_off[l];
    int cell = j / 9, a = j - cell * 9;
    int feat = c_lvl_feat[l];
    int row  = cell / feat, col = cell - row * feat;
    int stride = c_lvl_stride[l];

    float hh = s_hh[l * 9 + a];
    float hw = s_hw[l * 9 + a];

    float cy = ((float)row + 0.5f) * (float)stride;
    float cx = ((float)col + 0.5f) * (float)stride;
    float ay1 = __fsub_rn(cy, hh), ay2 = __fadd_rn(cy, hh);
    float ax1 = __fsub_rn(cx, hw), ax2 = __fadd_rn(cx, hw);
    float ah  = __fsub_rn(ay2, ay1), aw = __fsub_rn(ax2, ax1);
    float acy = __fmul_rn(__fadd_rn(ay1, ay2), 0.5f);
    float acx = __fmul_rn(__fadd_rn(ax1, ax2), 0.5f);

    float4 d = __ldg(deltas + (size_t)b * NANCH + n);
    float ncy = __fadd_rn(__fmul_rn(d.x, ah), acy);
    float ncx = __fadd_rn(__fmul_rn(d.y, aw), acx);
    float h   = __fmul_rn(expf(d.z), ah);
    float w   = __fmul_rn(expf(d.w), aw);

    const float inv = 1.0f / 512.0f;
    float y1 = __fsub_rn(ncy, __fmul_rn(h, 0.5f)) * inv;
    float x1 = __fsub_rn(ncx, __fmul_rn(w, 0.5f)) * inv;
    float y2 = __fadd_rn(ncy, __fmul_rn(h, 0.5f)) * inv;
    float x2 = __fadd_rn(ncx, __fmul_rn(w, 0.5f)) * inv;
    y1 = fminf(fmaxf(y1, 0.0f), 1.0f);
    x1 = fminf(fmaxf(x1, 0.0f), 1.0f);
    y2 = fminf(fmaxf(y2, 0.0f), 1.0f);
    x2 = fminf(fmaxf(x2, 0.0f), 1.0f);
    return make_float4(y1, x1, y2, x2);
}

// raw logit key in transposed order (fallback only; never hot)
__device__ __forceinline__ unsigned ldkey(const float* __restrict__ logits,
                                          int b, int c, int i) {
    return f2key(__ldg(logits + ((size_t)b * NANCH + i) * NCLS + c));
}

// ---------------- kernel 1: filter — warp per anchor, scatter final sort keys ----------------
__global__ void __launch_bounds__(256) k_filter(const float* __restrict__ logits) {
    int lane = threadIdx.x & 31;
    int gw = blockIdx.x * (blockDim.x >> 5) + (threadIdx.x >> 5);
    int nw = gridDim.x * (blockDim.x >> 5);
    for (int a = gw; a < NBATCH * NANCH; a += nw) {
        int b = a / NANCH, n = a - b * NANCH;
        const float* row = logits + (size_t)a * NCLS;
        #pragma unroll
        for (int j = 0; j < 3; ++j) {
            int c = lane + j * 32;
            if (c < NCLS) {
                float lg = __ldg(row + c);
                if (lg > FAST_LOGIT) {
                    int task = b * NCLS + c;
                    int slot = atomicAdd(&g_cnt[task], 1);
                    if (slot < CKCAP) {
                        float sc = __fdiv_rn(1.0f, __fadd_rn(1.0f, expf(-lg)));
                        g_bucket[(size_t)task * CKCAP + slot] =
                            ((u64)f2key(sc) << 17) | (u64)(131071 - n);
                    }
                }
            }
        }
    }
}

// ---------------- kernel 2: fast path — 128 thr, full sort + linear scan ----------------
__global__ void __launch_bounds__(TSK_T) k_task(const float4* __restrict__ deltas) {
    __shared__ u64    ck[CKCAP];       //  8 KB
    __shared__ float4 cboxes[CKCAP];   // 16 KB
    __shared__ float4 s_abox[KPOST];   // 1.6 KB
    __shared__ float  s_hh[45], s_hw[45];
    __shared__ int s_cnt, s_na, s_ok;

    int tid  = threadIdx.x;
    int lane = tid & 31;
    int task = blockIdx.x;
    int b    = task / NCLS;

    if (tid < 45) {
        int l = tid / 9, a = tid - l * 9;
        int stride = c_lvl_stride[l];
        int iscale = a / 3, ri = a - iscale * 3;
        double rr   = (ri == 0) ? 1.0 : (ri == 1 ? 0.5 : 2.0);
        double base = exp2((double)iscale / 3.0) * (double)stride * 4.0;
        double sq   = sqrt(rr);
        s_hh[tid] = (float)(base / sq / 2.0);
        s_hw[tid] = (float)(base * sq / 2.0);
    }
    if (tid == 0) { s_cnt = g_cnt[task]; g_cnt[task] = 0; }   // read + reset for next replay
    __syncthreads();
    int cnt = s_cnt;

    if (cnt > CKCAP) {                     // overflow -> exact fallback kernel
        if (tid == 0) g_ok[task] = 0;
        return;
    }

    // load bucket keys (already final sort keys)
    const u64* bk = g_bucket + (size_t)task * CKCAP;
    #pragma unroll
    for (int s = 0; s < CKCAP / TSK_T; ++s) {
        int i = tid + s * TSK_T;
        ck[i] = (i < cnt) ? __ldg(bk + i) : 0ull;
    }
    __syncthreads();

    // block-wide bitonic sort of 1024, descending (4 pairs/thread/round)
    for (int k2 = 2; k2 <= CKCAP; k2 <<= 1) {
        for (int j = k2 >> 1; j > 0; j >>= 1) {
            #pragma unroll
            for (int s = 0; s < CKCAP / (2 * TSK_T); ++s) {
                int p  = tid + s * TSK_T;
                int i  = ((p & ~(j - 1)) << 1) | (p & (j - 1));
                int ix = i | j;
                u64 a = ck[i], b2 = ck[ix];
                bool asc = ((i & k2) == 0);
                if ((a < b2) == asc) { ck[i] = b2; ck[ix] = a; }
            }
            __syncthreads();
        }
    }

    // decode boxes (sorted order)
    #pragma unroll
    for (int s = 0; s < CKCAP / TSK_T; ++s) {
        int i = tid + s * TSK_T;
        u64 k = ck[i];
        if (k) {
            int n = 131071 - (int)(k & 131071ull);
            cboxes[i] = decode_box(n, deltas, b, s_hh, s_hw);
        }
    }
    __syncthreads();

    // warp 0: linear sorted scan
    if (tid < 32) {
        int cna = 0, dn = 0;
        for (int f = 0; f < cnt; ++f) {
            u64 kk = ck[f];
            float sc = key2f((unsigned)(kk >> 17));
            if (!(sc > 0.2f)) { dn = 1; break; }
            float4 box = cboxes[f];
            bool sup = false;
            for (int a = lane; a < cna; a += 32)
                if (iou_gt(s_abox[a], box)) { sup = true; break; }
            if (!__any_sync(0xffffffffu, sup)) {
                if (lane == 0) {
                    g_nms_scores[(size_t)task * KPOST + cna] = sc;
                    g_nms_boxes [(size_t)task * KPOST + cna] = box;
                    s_abox[cna] = box;
                }
                __syncwarp();
                cna++;
                if (cna == KPOST) { dn = 1; break; }
            }
        }
        if (lane == 0) { s_na = cna; s_ok = dn; }
    }
    __syncthreads();
    if (tid == 0) g_ok[task] = s_ok;
    if (s_ok) {
        for (int q = s_na + tid; q < KPOST; q += TSK_T) {
            g_nms_scores[(size_t)task * KPOST + q] = 0.0f;
            g_nms_boxes [(size_t)task * KPOST + q] = make_float4(0.f, 0.f, 0.f, 0.f);
        }
    }
}

// ---------------- kernel 2b: exact fallback (early-exit when fast path succeeded) ----------------
__global__ void __launch_bounds__(FLB_T) k_fallback(const float4* __restrict__ deltas,
                                                    const float* __restrict__ logits) {
    int task = blockIdx.x;
    if (g_ok[task]) return;                 // uniform per block

    __shared__ unsigned hist[2048];
    __shared__ u64      ck[CKCAP];
    __shared__ float4   cboxes[CKCAP];
    __shared__ float4   s_abox[KPOST];
    __shared__ unsigned wA[16], wB[16];
    __shared__ float    s_hh[45], s_hw[45];
    __shared__ int s_bcv, s_bck, s_cnt, s_na, s_done;
    __shared__ unsigned s_total;

    int tid  = threadIdx.x;
    int lane = tid & 31;
    int b    = task / NCLS;
    int c    = task - b * NCLS;

    if (tid < 45) {
        int l = tid / 9, a = tid - l * 9;
        int stride = c_lvl_stride[l];
        int iscale = a / 3, ri = a - iscale * 3;
        double rr   = (ri == 0) ? 1.0 : (ri == 1 ? 0.5 : 2.0);
        double base = exp2((double)iscale / 3.0) * (double)stride * 4.0;
        double sq   = sqrt(rr);
        s_hh[tid] = (float)(base / sq / 2.0);
        s_hw[tid] = (float)(base * sq / 2.0);
    }
    if (tid == 0) { s_na = 0; s_done = 0; }
    __syncthreads();

    unsigned Tprev = 0;
    bool first = true;
    int cand_base = 0;

    for (;;) {
        unsigned prefix = 0;
        int Krem = KBATCH;
        bool allin = false;
        const int SH[3] = {21, 10, 0};
        const int BT[3] = {11, 11, 10};
        for (int pass = 0; pass < 3; ++pass) {
            int shift = SH[pass], bits = BT[pass], nb = 1 << bits, top = shift + bits;
            for (int i = tid; i < nb; i += FLB_T) hist[i] = 0;
            __syncthreads();
            for (int base = 0; base < NANCH; base += FLB_T) {
                int i = base + tid;
                bool inb = i < NANCH;
                unsigned k = inb ? ldkey(logits, b, c, i) : 0u;
                bool valid = inb && (first || k < Tprev) &&
                             (pass == 0 || (k >> top) == prefix);
                unsigned bin = (k >> shift) & (unsigned)(nb - 1);
                unsigned tag = valid ? bin : 0xffffffffu;
                unsigned m = __match_any_sync(0xffffffffu, tag);
                if (valid && (__ffs(m) - 1) == lane)
                    atomicAdd(&hist[bin], (unsigned)__popc(m));
            }
            __syncthreads();
            int cs = nb >> 9;
            int base0 = tid * cs;
            unsigned ssum = 0;
            for (int j = 0; j < cs; ++j) ssum += hist[base0 + j];
            unsigned St = sufscan512(ssum, wA, wB);
            if (pass == 0 && tid == 0) s_total = St;
            if (St >= (unsigned)Krem && (St - ssum) < (unsigned)Krem) {
                unsigned acc = St - ssum;
                for (int j = cs - 1; j >= 0; --j) {
                    unsigned hv = hist[base0 + j];
                    acc += hv;
                    if (acc >= (unsigned)Krem) {
                        s_bcv = base0 + j;
                        s_bck = Krem - (int)(acc - hv);
                        break;
                    }
                }
            }
            __syncthreads();
            if (pass == 0 && s_total <= (unsigned)KBATCH) { allin = true; break; }
            prefix = (prefix << bits) | (unsigned)s_bcv;
            Krem   = s_bck;
            __syncthreads();
        }
        unsigned T = allin ? 0u : prefix;

        if (tid == 0) s_cnt = 0;
        __syncthreads();
        for (int base = 0; base < NANCH; base += FLB_T) {
            int i = base + tid;
            bool inb = i < NANCH;
            unsigned k = inb ? ldkey(logits, b, c, i) : 0u;
            bool pred = inb && (first || k < Tprev) && (k >= T);
            unsigned mask = __ballot_sync(0xffffffffu, pred);
            if (pred) {
                int leader = __ffs(mask) - 1;
                int bslot = 0;
                if (lane == leader) bslot = atomicAdd(&s_cnt, __popc(mask));
                bslot = __shfl_sync(mask, bslot, leader);
                int slot = bslot + __popc(mask & ((1u << lane) - 1u));
                if (slot < CKCAP) {
                    float logit = key2f(k);
                    float sc = __fdiv_rn(1.0f, __fadd_rn(1.0f, expf(-logit)));
                    ck[slot] = ((u64)f2key(sc) << 17) | (u64)(131071 - i);
                }
            }
        }
        __syncthreads();
        int M = min(s_cnt, CKCAP);
        for (int i = M + tid; i < CKCAP; i += FLB_T) ck[i] = 0ull;
        __syncthreads();

        for (int k2 = 2; k2 <= CKCAP; k2 <<= 1) {
            for (int j = k2 >> 1; j > 0; j >>= 1) {
                int i  = ((tid & ~(j - 1)) << 1) | (tid & (j - 1));
                int ix = i | j;
                bool asc = ((i & k2) == 0);
                u64 a = ck[i], b2 = ck[ix];
                if ((a < b2) == asc) { ck[i] = b2; ck[ix] = a; }
                __syncthreads();
            }
        }

        for (int i = tid; i < M; i += FLB_T) {
            int n = 131071 - (int)(ck[i] & 131071ull);
            cboxes[i] = decode_box(n, deltas, b, s_hh, s_hw);
        }
        __syncthreads();

        if (tid < 32) {
            int cna = s_na;
            int dn  = 0;
            for (int f = 0; f < M; ++f) {
                if (cand_base + f >= KPRE) { dn = 1; break; }
                u64 kk = ck[f];
                float sc = key2f((unsigned)(kk >> 17));
                if (!(sc > 0.2f)) { dn = 1; break; }
                float4 box = cboxes[f];
                bool sup = false;
                for (int a = lane; a < cna; a += 32)
                    if (iou_gt(s_abox[a], box)) { sup = true; break; }
                if (!__any_sync(0xffffffffu, sup)) {
                    if (lane == 0) {
                        g_nms_scores[(size_t)task * KPOST + cna] = sc;
                        g_nms_boxes [(size_t)task * KPOST + cna] = box;
                        s_abox[cna] = box;
                    }
                    __syncwarp();
                    cna++;
                    if (cna == KPOST) { dn = 1; break; }
                }
            }
            if (lane == 0) { s_na = cna; s_done = dn; }
        }
        __syncthreads();
        cand_base += M;
        if (s_done || allin || M == 0 || cand_base >= KPRE) break;
        Tprev = T;
        first = false;
        __syncthreads();
    }

    for (int q = s_na + tid; q < KPOST; q += FLB_T) {
        g_nms_scores[(size_t)task * KPOST + q] = 0.0f;
        g_nms_boxes [(size_t)task * KPOST + q] = make_float4(0.f, 0.f, 0.f, 0.f);
    }
}

// ---------------- kernel 3: per-batch top-100 of 9000 (radix select + rank) ----------------
extern __shared__ u64 smF[];
__global__ void __launch_bounds__(FIN_T) k_final(float* __restrict__ out) {
    u64*      ck   = smF;                             // [9000]
    unsigned* hist = (unsigned*)(smF + NCLS * KPOST); // [4096]
    __shared__ unsigned wA[16], wB[16];
    __shared__ int s_bcv, s_bck, s_cnt, s_valid;
    __shared__ u64 surv[KPOST];

    int b = blockIdx.x, tid = threadIdx.x;
    const float* src = g_nms_scores + (size_t)b * NCLS * KPOST;
    for (int i = tid; i < NCLS * KPOST; i += FIN_T)
        ck[i] = ((u64)f2key(src[i]) << 14) | (u64)(16383 - i);
    if (tid == 0) { s_cnt = 0; s_valid = 0; }
    __syncthreads();

    u64 pref = 0; int Krem = KPOST;
    const int SHs[4] = {34, 22, 10, 0};
    const int BTs[4] = {12, 12, 12, 10};
    for (int p = 0; p < 4; ++p) {
        int shift = SHs[p], bits = BTs[p], nb = 1 << bits, top = shift + bits;
        for (int i = tid; i < nb; i += FIN_T) hist[i] = 0;
        __syncthreads();
        for (int i = tid; i < NCLS * KPOST; i += FIN_T) {
            u64 k = ck[i];
            if ((k >> top) == pref)
                atomicAdd(&hist[(unsigned)((k >> shift) & (u64)(nb - 1))], 1u);
        }
        __syncthreads();
        int csz = nb >> 9; if (csz == 0) csz = 1;
        int base0 = tid * csz;
        unsigned ssum = 0;
        for (int j = 0; j < csz; ++j) ssum += hist[base0 + j];
        unsigned St = sufscan512(ssum, wA, wB);
        if (St >= (unsigned)Krem && (St - ssum) < (unsigned)Krem) {
            unsigned acc = St - ssum;
            for (int j = csz - 1; j >= 0; --j) {
                unsigned hv = hist[base0 + j];
                acc += hv;
                if (acc >= (unsigned)Krem) {
                    s_bcv = base0 + j;
                    s_bck = Krem - (int)(acc - hv);
                    break;
                }
            }
        }
        __syncthreads();
        pref = (pref << bits) | (u64)(unsigned)s_bcv;
        Krem = s_bck;
        __syncthreads();
    }
    u64 T = pref;

    for (int i = tid; i < NCLS * KPOST; i += FIN_T) {
        u64 k = ck[i];
        if (k >= T) {
            int slot = atomicAdd(&s_cnt, 1);
            if (slot < KPOST) surv[slot] = k;
        }
    }
    __syncthreads();

    if (tid < KPOST) {
        u64 k = surv[tid];
        int rank = 0;
        #pragma unroll 4
        for (int j = 0; j < KPOST; ++j) rank += (surv[j] > k);
        int flat = 16383 - (int)(k & 16383ull);
        float sc = key2f((unsigned)(k >> 14));
        float4 bb = g_nms_boxes[(size_t)b * NCLS * KPOST + flat];
        float* ob = out + ((size_t)b * KPOST + rank) * 4;
        ob[0] = bb.x; ob[1] = bb.y; ob[2] = bb.z; ob[3] = bb.w;
        out[NBATCH * KPOST * 4 + b * KPOST + rank] = sc;
        out[NBATCH * KPOST * 5 + b * KPOST + rank] = (float)(flat / KPOST);
        if (sc > 0.0f) atomicAdd(&s_valid, 1);
    }
    __syncthreads();
    if (tid == 0) out[NBATCH * KPOST * 6 + b] = (float)s_valid;
}

// ---------------- launch ----------------
extern "C" void kernel_launch(void* const* d_in, const int* in_sizes, int n_in,
                              void* d_out, int out_size) {
    const float* a0 = (const float*)d_in[0];
    const float* a1 = (const float*)d_in[1];
    const float4* deltas;
    const float*  logits;
    if (in_sizes[0] == NBATCH * NANCH * 4) { deltas = (const float4*)a0; logits = a1; }
    else                                   { deltas = (const float4*)a1; logits = a0; }
    float* out = (float*)d_out;

    const int finSm = NCLS * KPOST * 8 + 4096 * 4;   // 88,384
    cudaFuncSetAttribute(k_final, cudaFuncAttributeMaxDynamicSharedMemorySize, finSm);

    k_filter<<<2048, 256>>>(logits);
    k_task<<<NTASK, TSK_T>>>(deltas);
    k_fallback<<<NTASK, FLB_T>>>(deltas, logits);
    k_final<<<NBATCH, FIN_T, finSm>>>(out);
}

// round 15
// speedup vs baseline: 1.3786x; 1.1521x over previous
#include <cuda_runtime.h>
#include <math.h>

#define NANCH 49104
#define NCLS  90
#define NBATCH 8
#define NTASK (NBATCH * NCLS)   // 720
#define KPRE  5000
#define KPOST 100
#define KBATCH 256              // fallback per-batch select size
#define CKCAP 1024              // bucket capacity / sort size
#define TSK_T 128
#define FLB_T 512
#define FIN_T 512
#define FAST_LOGIT 2.2f         // fast-path threshold (count ~680 << 1024)

typedef unsigned long long u64;

// ---------------- scratch (zero-initialized at module load) ----------------
__device__ int      g_cnt[NTASK];
__device__ int      g_ok[NTASK];
__device__ u64      g_bucket[(size_t)NTASK * CKCAP];    // (f2key(sigmoid)<<17 | 131071-n)
__device__ float4   g_nms_boxes[NTASK * KPOST];
__device__ float    g_nms_scores[NTASK * KPOST];

__constant__ int c_lvl_off[6]    = {0, 36864, 46080, 48384, 48960, 49104};
__constant__ int c_lvl_feat[5]   = {64, 32, 16, 8, 4};
__constant__ int c_lvl_stride[5] = {8, 16, 32, 64, 128};

__device__ __forceinline__ unsigned f2key(float f) {
    unsigned u = __float_as_uint(f);
    return (u & 0x80000000u) ? ~u : (u | 0x80000000u);
}
__device__ __forceinline__ float key2f(unsigned k) {
    unsigned u = (k & 0x80000000u) ? (k ^ 0x80000000u) : ~k;
    return __uint_as_float(u);
}

__device__ __forceinline__ bool iou_gt(const float4 a, const float4 b) {
    float yy1 = fmaxf(a.x, b.x), xx1 = fmaxf(a.y, b.y);
    float yy2 = fminf(a.z, b.z), xx2 = fminf(a.w, b.w);
    float ih = fmaxf(__fsub_rn(yy2, yy1), 0.0f);
    float iw = fmaxf(__fsub_rn(xx2, xx1), 0.0f);
    float inter = __fmul_rn(ih, iw);
    float a1 = __fmul_rn(__fsub_rn(a.z, a.x), __fsub_rn(a.w, a.y));
    float a2 = __fmul_rn(__fsub_rn(b.z, b.x), __fsub_rn(b.w, b.y));
    float den = __fadd_rn(__fsub_rn(__fadd_rn(a1, a2), inter), 1e-8f);
    return __fdiv_rn(inter, den) > 0.5f;
}

// inclusive SUFFIX scan over 512 per-thread values (blockDim must be 512)
__device__ __forceinline__ unsigned sufscan512(unsigned ssum, unsigned* wA, unsigned* wB) {
    int lane = threadIdx.x & 31, wrp = threadIdx.x >> 5;
    unsigned s = ssum;
    #pragma unroll
    for (int o = 1; o < 32; o <<= 1) {
        unsigned t = __shfl_down_sync(0xffffffffu, s, o);
        if (lane + o < 32) s += t;
    }
    if (lane == 0) wA[wrp] = s;
    __syncthreads();
    if (threadIdx.x < 32) {
        unsigned v = (threadIdx.x < 16) ? wA[threadIdx.x] : 0u;
        unsigned sv = v;
        #pragma unroll
        for (int o = 1; o < 32; o <<= 1) {
            unsigned t = __shfl_down_sync(0xffffffffu, sv, o);
            if (threadIdx.x + o < 32) sv += t;
        }
        if (threadIdx.x < 16) wB[threadIdx.x] = sv - v;
    }
    __syncthreads();
    return s + wB[wrp];
}

__device__ __forceinline__ float4 decode_box(int n, const float4* __restrict__ deltas,
                                             int b, const float* s_hh, const float* s_hw) {
    int l = 0;
    #pragma unroll
    for (int q = 1; q < 5; ++q) if (n >= c_lvl_off[q]) l = q;
    int j    = n - c_lvl_off[l];
    int cell = j / 9, a = j - cell * 9;
    int feat = c_lvl_feat[l];
    int row  = cell / feat, col = cell - row * feat;
    int stride = c_lvl_stride[l];

    float hh = s_hh[l * 9 + a];
    float hw = s_hw[l * 9 + a];

    float cy = ((float)row + 0.5f) * (float)stride;
    float cx = ((float)col + 0.5f) * (float)stride;
    float ay1 = __fsub_rn(cy, hh), ay2 = __fadd_rn(cy, hh);
    float ax1 = __fsub_rn(cx, hw), ax2 = __fadd_rn(cx, hw);
    float ah  = __fsub_rn(ay2, ay1), aw = __fsub_rn(ax2, ax1);
    float acy = __fmul_rn(__fadd_rn(ay1, ay2), 0.5f);
    float acx = __fmul_rn(__fadd_rn(ax1, ax2), 0.5f);

    float4 d = __ldg(deltas + (size_t)b * NANCH + n);
    float ncy = __fadd_rn(__fmul_rn(d.x, ah), acy);
    float ncx = __fadd_rn(__fmul_rn(d.y, aw), acx);
    float h   = __fmul_rn(expf(d.z), ah);
    float w   = __fmul_rn(expf(d.w), aw);

    const float inv = 1.0f / 512.0f;
    float y1 = __fsub_rn(ncy, __fmul_rn(h, 0.5f)) * inv;
    float x1 = __fsub_rn(ncx, __fmul_rn(w, 0.5f)) * inv;
    float y2 = __fadd_rn(ncy, __fmul_rn(h, 0.5f)) * inv;
    float x2 = __fadd_rn(ncx, __fmul_rn(w, 0.5f)) * inv;
    y1 = fminf(fmaxf(y1, 0.0f), 1.0f);
    x1 = fminf(fmaxf(x1, 0.0f), 1.0f);
    y2 = fminf(fmaxf(y2, 0.0f), 1.0f);
    x2 = fminf(fmaxf(x2, 0.0f), 1.0f);
    return make_float4(y1, x1, y2, x2);
}

// raw logit key in transposed order (fallback only; never hot)
__device__ __forceinline__ unsigned ldkey(const float* __restrict__ logits,
                                          int b, int c, int i) {
    return f2key(__ldg(logits + ((size_t)b * NANCH + i) * NCLS + c));
}

// ---------------- kernel 1: filter — flat float4 stream, scatter final sort keys ----------------
__global__ void __launch_bounds__(256) k_filter(const float4* __restrict__ logits4) {
    const int total4 = NBATCH * NANCH * NCLS / 4;   // 8,838,720
    int stride = gridDim.x * blockDim.x;
    for (int i = blockIdx.x * blockDim.x + threadIdx.x; i < total4; i += stride) {
        float4 v = __ldg(logits4 + i);
        int fbase = i * 4;
        #pragma unroll
        for (int q = 0; q < 4; ++q) {
            float lg = (q == 0) ? v.x : (q == 1) ? v.y : (q == 2) ? v.z : v.w;
            if (lg > FAST_LOGIT) {
                int fidx = fbase + q;
                int a = fidx / NCLS;
                int c = fidx - a * NCLS;
                int b = a / NANCH;
                int n = a - b * NANCH;
                int task = b * NCLS + c;
                int slot = atomicAdd(&g_cnt[task], 1);
                if (slot < CKCAP) {
                    float sc = __fdiv_rn(1.0f, __fadd_rn(1.0f, expf(-lg)));
                    g_bucket[(size_t)task * CKCAP + slot] =
                        ((u64)f2key(sc) << 17) | (u64)(131071 - n);
                }
            }
        }
    }
}

// ---------------- kernel 2: fast path — 128 thr, full sort + linear scan ----------------
__global__ void __launch_bounds__(TSK_T) k_task(const float4* __restrict__ deltas) {
    __shared__ u64    ck[CKCAP];       //  8 KB
    __shared__ float4 cboxes[CKCAP];   // 16 KB
    __shared__ float4 s_abox[KPOST];   // 1.6 KB
    __shared__ float  s_hh[45], s_hw[45];
    __shared__ int s_cnt, s_na, s_ok;

    int tid  = threadIdx.x;
    int lane = tid & 31;
    int task = blockIdx.x;
    int b    = task / NCLS;

    if (tid < 45) {
        int l = tid / 9, a = tid - l * 9;
        int stride = c_lvl_stride[l];
        int iscale = a / 3, ri = a - iscale * 3;
        double rr   = (ri == 0) ? 1.0 : (ri == 1 ? 0.5 : 2.0);
        double base = exp2((double)iscale / 3.0) * (double)stride * 4.0;
        double sq   = sqrt(rr);
        s_hh[tid] = (float)(base / sq / 2.0);
        s_hw[tid] = (float)(base * sq / 2.0);
    }
    if (tid == 0) { s_cnt = g_cnt[task]; g_cnt[task] = 0; }   // read + reset for next replay
    __syncthreads();
    int cnt = s_cnt;

    if (cnt > CKCAP) {                     // overflow -> exact fallback kernel
        if (tid == 0) g_ok[task] = 0;
        return;
    }

    // load bucket keys (already final sort keys)
    const u64* bk = g_bucket + (size_t)task * CKCAP;
    #pragma unroll
    for (int s = 0; s < CKCAP / TSK_T; ++s) {
        int i = tid + s * TSK_T;
        ck[i] = (i < cnt) ? __ldg(bk + i) : 0ull;
    }
    __syncthreads();

    // block-wide bitonic sort of 1024, descending (4 pairs/thread/round)
    for (int k2 = 2; k2 <= CKCAP; k2 <<= 1) {
        for (int j = k2 >> 1; j > 0; j >>= 1) {
            #pragma unroll
            for (int s = 0; s < CKCAP / (2 * TSK_T); ++s) {
                int p  = tid + s * TSK_T;
                int i  = ((p & ~(j - 1)) << 1) | (p & (j - 1));
                int ix = i | j;
                u64 a = ck[i], b2 = ck[ix];
                bool asc = ((i & k2) == 0);
                if ((a < b2) == asc) { ck[i] = b2; ck[ix] = a; }
            }
            __syncthreads();
        }
    }

    // decode boxes (sorted order)
    #pragma unroll
    for (int s = 0; s < CKCAP / TSK_T; ++s) {
        int i = tid + s * TSK_T;
        u64 k = ck[i];
        if (k) {
            int n = 131071 - (int)(k & 131071ull);
            cboxes[i] = decode_box(n, deltas, b, s_hh, s_hw);
        }
    }
    __syncthreads();

    // warp 0: linear sorted scan
    if (tid < 32) {
        int cna = 0, dn = 0;
        for (int f = 0; f < cnt; ++f) {
            u64 kk = ck[f];
            float sc = key2f((unsigned)(kk >> 17));
            if (!(sc > 0.2f)) { dn = 1; break; }
            float4 box = cboxes[f];
            bool sup = false;
            for (int a = lane; a < cna; a += 32)
                if (iou_gt(s_abox[a], box)) { sup = true; break; }
            if (!__any_sync(0xffffffffu, sup)) {
                if (lane == 0) {
                    g_nms_scores[(size_t)task * KPOST + cna] = sc;
                    g_nms_boxes [(size_t)task * KPOST + cna] = box;
                    s_abox[cna] = box;
                }
                __syncwarp();
                cna++;
                if (cna == KPOST) { dn = 1; break; }
            }
        }
        if (lane == 0) { s_na = cna; s_ok = dn; }
    }
    __syncthreads();
    if (tid == 0) g_ok[task] = s_ok;
    if (s_ok) {
        for (int q = s_na + tid; q < KPOST; q += TSK_T) {
            g_nms_scores[(size_t)task * KPOST + q] = 0.0f;
            g_nms_boxes [(size_t)task * KPOST + q] = make_float4(0.f, 0.f, 0.f, 0.f);
        }
    }
}

// ---------------- kernel 2b: exact fallback (early-exit when fast path succeeded) ----------------
__global__ void __launch_bounds__(FLB_T) k_fallback(const float4* __restrict__ deltas,
                                                    const float* __restrict__ logits) {
    int task = blockIdx.x;
    if (g_ok[task]) return;                 // uniform per block

    __shared__ unsigned hist[2048];
    __shared__ u64      ck[CKCAP];
    __shared__ float4   cboxes[CKCAP];
    __shared__ float4   s_abox[KPOST];
    __shared__ unsigned wA[16], wB[16];
    __shared__ float    s_hh[45], s_hw[45];
    __shared__ int s_bcv, s_bck, s_cnt, s_na, s_done;
    __shared__ unsigned s_total;

    int tid  = threadIdx.x;
    int lane = tid & 31;
    int b    = task / NCLS;
    int c    = task - b * NCLS;

    if (tid < 45) {
        int l = tid / 9, a = tid - l * 9;
        int stride = c_lvl_stride[l];
        int iscale = a / 3, ri = a - iscale * 3;
        double rr   = (ri == 0) ? 1.0 : (ri == 1 ? 0.5 : 2.0);
        double base = exp2((double)iscale / 3.0) * (double)stride * 4.0;
        double sq   = sqrt(rr);
        s_hh[tid] = (float)(base / sq / 2.0);
        s_hw[tid] = (float)(base * sq / 2.0);
    }
    if (tid == 0) { s_na = 0; s_done = 0; }
    __syncthreads();

    unsigned Tprev = 0;
    bool first = true;
    int cand_base = 0;

    for (;;) {
        unsigned prefix = 0;
        int Krem = KBATCH;
        bool allin = false;
        const int SH[3] = {21, 10, 0};
        const int BT[3] = {11, 11, 10};
        for (int pass = 0; pass < 3; ++pass) {
            int shift = SH[pass], bits = BT[pass], nb = 1 << bits, top = shift + bits;
            for (int i = tid; i < nb; i += FLB_T) hist[i] = 0;
            __syncthreads();
            for (int base = 0; base < NANCH; base += FLB_T) {
                int i = base + tid;
                bool inb = i < NANCH;
                unsigned k = inb ? ldkey(logits, b, c, i) : 0u;
                bool valid = inb && (first || k < Tprev) &&
                             (pass == 0 || (k >> top) == prefix);
                unsigned bin = (k >> shift) & (unsigned)(nb - 1);
                unsigned tag = valid ? bin : 0xffffffffu;
                unsigned m = __match_any_sync(0xffffffffu, tag);
                if (valid && (__ffs(m) - 1) == lane)
                    atomicAdd(&hist[bin], (unsigned)__popc(m));
            }
            __syncthreads();
            int cs = nb >> 9;
            int base0 = tid * cs;
            unsigned ssum = 0;
            for (int j = 0; j < cs; ++j) ssum += hist[base0 + j];
            unsigned St = sufscan512(ssum, wA, wB);
            if (pass == 0 && tid == 0) s_total = St;
            if (St >= (unsigned)Krem && (St - ssum) < (unsigned)Krem) {
                unsigned acc = St - ssum;
                for (int j = cs - 1; j >= 0; --j) {
                    unsigned hv = hist[base0 + j];
                    acc += hv;
                    if (acc >= (unsigned)Krem) {
                        s_bcv = base0 + j;
                        s_bck = Krem - (int)(acc - hv);
                        break;
                    }
                }
            }
            __syncthreads();
            if (pass == 0 && s_total <= (unsigned)KBATCH) { allin = true; break; }
            prefix = (prefix << bits) | (unsigned)s_bcv;
            Krem   = s_bck;
            __syncthreads();
        }
        unsigned T = allin ? 0u : prefix;

        if (tid == 0) s_cnt = 0;
        __syncthreads();
        for (int base = 0; base < NANCH; base += FLB_T) {
            int i = base + tid;
            bool inb = i < NANCH;
            unsigned k = inb ? ldkey(logits, b, c, i) : 0u;
            bool pred = inb && (first || k < Tprev) && (k >= T);
            unsigned mask = __ballot_sync(0xffffffffu, pred);
            if (pred) {
                int leader = __ffs(mask) - 1;
                int bslot = 0;
                if (lane == leader) bslot = atomicAdd(&s_cnt, __popc(mask));
                bslot = __shfl_sync(mask, bslot, leader);
                int slot = bslot + __popc(mask & ((1u << lane) - 1u));
                if (slot < CKCAP) {
                    float logit = key2f(k);
                    float sc = __fdiv_rn(1.0f, __fadd_rn(1.0f, expf(-logit)));
                    ck[slot] = ((u64)f2key(sc) << 17) | (u64)(131071 - i);
                }
            }
        }
        __syncthreads();
        int M = min(s_cnt, CKCAP);
        for (int i = M + tid; i < CKCAP; i += FLB_T) ck[i] = 0ull;
        __syncthreads();

        for (int k2 = 2; k2 <= CKCAP; k2 <<= 1) {
            for (int j = k2 >> 1; j > 0; j >>= 1) {
                int i  = ((tid & ~(j - 1)) << 1) | (tid & (j - 1));
                int ix = i | j;
                bool asc = ((i & k2) == 0);
                u64 a = ck[i], b2 = ck[ix];
                if ((a < b2) == asc) { ck[i] = b2; ck[ix] = a; }
                __syncthreads();
            }
        }

        for (int i = tid; i < M; i += FLB_T) {
            int n = 131071 - (int)(ck[i] & 131071ull);
            cboxes[i] = decode_box(n, deltas, b, s_hh, s_hw);
        }
        __syncthreads();

        if (tid < 32) {
            int cna = s_na;
            int dn  = 0;
            for (int f = 0; f < M; ++f) {
                if (cand_base + f >= KPRE) { dn = 1; break; }
                u64 kk = ck[f];
                float sc = key2f((unsigned)(kk >> 17));
                if (!(sc > 0.2f)) { dn = 1; break; }
                float4 box = cboxes[f];
                bool sup = false;
                for (int a = lane; a < cna; a += 32)
                    if (iou_gt(s_abox[a], box)) { sup = true; break; }
                if (!__any_sync(0xffffffffu, sup)) {
                    if (lane == 0) {
                        g_nms_scores[(size_t)task * KPOST + cna] = sc;
                        g_nms_boxes [(size_t)task * KPOST + cna] = box;
                        s_abox[cna] = box;
                    }
                    __syncwarp();
                    cna++;
                    if (cna == KPOST) { dn = 1; break; }
                }
            }
            if (lane == 0) { s_na = cna; s_done = dn; }
        }
        __syncthreads();
        cand_base += M;
        if (s_done || allin || M == 0 || cand_base >= KPRE) break;
        Tprev = T;
        first = false;
        __syncthreads();
    }

    for (int q = s_na + tid; q < KPOST; q += FLB_T) {
        g_nms_scores[(size_t)task * KPOST + q] = 0.0f;
        g_nms_boxes [(size_t)task * KPOST + q] = make_float4(0.f, 0.f, 0.f, 0.f);
    }
}

// ---------------- kernel 3: per-batch top-100 of 9000 (radix select + rank) ----------------
extern __shared__ u64 smF[];
__global__ void __launch_bounds__(FIN_T) k_final(float* __restrict__ out) {
    u64*      ck   = smF;                             // [9000]
    unsigned* hist = (unsigned*)(smF + NCLS * KPOST); // [4096]
    __shared__ unsigned wA[16], wB[16];
    __shared__ int s_bcv, s_bck, s_cnt, s_valid;
    __shared__ u64 surv[KPOST];

    int b = blockIdx.x, tid = threadIdx.x;
    int lane = tid & 31;
    const float* src = g_nms_scores + (size_t)b * NCLS * KPOST;
    for (int i = tid; i < NCLS * KPOST; i += FIN_T)
        ck[i] = ((u64)f2key(src[i]) << 14) | (u64)(16383 - i);
    if (tid == 0) { s_cnt = 0; s_valid = 0; }
    __syncthreads();

    u64 pref = 0; int Krem = KPOST;
    const int SHs[4] = {34, 22, 10, 0};
    const int BTs[4] = {12, 12, 12, 10};
    for (int p = 0; p < 4; ++p) {
        int shift = SHs[p], bits = BTs[p], nb = 1 << bits, top = shift + bits;
        for (int i = tid; i < nb; i += FIN_T) hist[i] = 0;
        __syncthreads();
        // warp-aggregated histogram (keys are exponent-clustered -> hot bins)
        for (int base = 0; base < NCLS * KPOST; base += FIN_T) {
            int i = base + tid;
            bool inb = i < NCLS * KPOST;
            u64 k = inb ? ck[i] : 0ull;
            bool valid = inb && ((k >> top) == pref);
            unsigned bin = (unsigned)((k >> shift) & (u64)(nb - 1));
            unsigned tag = valid ? bin : 0xffffffffu;
            unsigned m = __match_any_sync(0xffffffffu, tag);
            if (valid && (__ffs(m) - 1) == lane)
                atomicAdd(&hist[bin], (unsigned)__popc(m));
        }
        __syncthreads();
        int csz = nb >> 9; if (csz == 0) csz = 1;
        int base0 = tid * csz;
        unsigned ssum = 0;
        for (int j = 0; j < csz; ++j) ssum += hist[base0 + j];
        unsigned St = sufscan512(ssum, wA, wB);
        if (St >= (unsigned)Krem && (St - ssum) < (unsigned)Krem) {
            unsigned acc = St - ssum;
            for (int j = csz - 1; j >= 0; --j) {
                unsigned hv = hist[base0 + j];
                acc += hv;
                if (acc >= (unsigned)Krem) {
                    s_bcv = base0 + j;
                    s_bck = Krem - (int)(acc - hv);
                    break;
                }
            }
        }
        __syncthreads();
        pref = (pref << bits) | (u64)(unsigned)s_bcv;
        Krem = s_bck;
        __syncthreads();
    }
    u64 T = pref;

    for (int i = tid; i < NCLS * KPOST; i += FIN_T) {
        u64 k = ck[i];
        if (k >= T) {
            int slot = atomicAdd(&s_cnt, 1);
            if (slot < KPOST) surv[slot] = k;
        }
    }
    __syncthreads();

    if (tid < KPOST) {
        u64 k = surv[tid];
        int rank = 0;
        #pragma unroll 4
        for (int j = 0; j < KPOST; ++j) rank += (surv[j] > k);
        int flat = 16383 - (int)(k & 16383ull);
        float sc = key2f((unsigned)(k >> 14));
        float4 bb = g_nms_boxes[(size_t)b * NCLS * KPOST + flat];
        float* ob = out + ((size_t)b * KPOST + rank) * 4;
        ob[0] = bb.x; ob[1] = bb.y; ob[2] = bb.z; ob[3] = bb.w;
        out[NBATCH * KPOST * 4 + b * KPOST + rank] = sc;
        out[NBATCH * KPOST * 5 + b * KPOST + rank] = (float)(flat / KPOST);
        if (sc > 0.0f) atomicAdd(&s_valid, 1);
    }
    __syncthreads();
    if (tid == 0) out[NBATCH * KPOST * 6 + b] = (float)s_valid;
}

// ---------------- launch ----------------
extern "C" void kernel_launch(void* const* d_in, const int* in_sizes, int n_in,
                              void* d_out, int out_size) {
    const float* a0 = (const float*)d_in[0];
    const float* a1 = (const float*)d_in[1];
    const float4* deltas;
    const float*  logits;
    if (in_sizes[0] == NBATCH * NANCH * 4) { deltas = (const float4*)a0; logits = a1; }
    else                                   { deltas = (const float4*)a1; logits = a0; }
    float* out = (float*)d_out;

    const int finSm = NCLS * KPOST * 8 + 4096 * 4;   // 88,384
    cudaFuncSetAttribute(k_final, cudaFuncAttributeMaxDynamicSharedMemorySize, finSm);

    k_filter<<<4096, 256>>>((const float4*)logits);
    k_task<<<NTASK, TSK_T>>>(deltas);
    k_fallback<<<NTASK, FLB_T>>>(deltas, logits);
    k_final<<<NBATCH, FIN_T, finSm>>>(out);
}